// round 1
// baseline (speedup 1.0000x reference)
#include <cuda_runtime.h>
#include <math.h>

#define N_NODES 20000
#define N_EDGES 320000
#define D_IN    160
#define PRE     384   // per-node precompute floats: 64*(R,U0,U1,U2) + 32*(P,Q0,Q1,Q2)

// Static device scratch (no dynamic allocation allowed)
__device__ float g_M0[96 * 64];          // combined W0@V0 (scaled, rows 64.. include 1/sqrt3)
__device__ float g_M1[96 * 32];          // combined W1@V1 (scaled)
__device__ float g_pre[(size_t)N_NODES * PRE];  // ~30.7 MB

// ---------------------------------------------------------------------------
// Kernel 0: zero the output/accumulator buffer (poisoned by harness)
// ---------------------------------------------------------------------------
__global__ void zero_kernel(float4* __restrict__ out, int n4) {
    int i = blockIdx.x * blockDim.x + threadIdx.x;
    if (i < n4) out[i] = make_float4(0.f, 0.f, 0.f, 0.f);
}

// ---------------------------------------------------------------------------
// Kernel 1: build combined matrices M0 = W0@V0 * s0, M1 = W1@V1 * s1
// ---------------------------------------------------------------------------
__global__ void build_M(const float* __restrict__ W0, const float* __restrict__ W1,
                        const float* __restrict__ V0, const float* __restrict__ V1) {
    int t = blockIdx.x * blockDim.x + threadIdx.x;
    if (t < 96 * 64) {
        int u = t >> 6, c = t & 63;
        float acc = 0.f;
        #pragma unroll 8
        for (int k = 0; k < 128; ++k) acc += W0[u * 128 + k] * V0[k * 64 + c];
        float s = 1.0f / sqrtf(96.0f * 128.0f);
        if (u >= 64) s *= 0.5773502691896258f;   // fold 1/sqrt(3) from D into lower rows
        g_M0[t] = acc * s;
    } else if (t < 96 * 64 + 96 * 32) {
        int t2 = t - 96 * 64;
        int u = t2 >> 5, w = t2 & 31;
        float acc = 0.f;
        #pragma unroll 8
        for (int k = 0; k < 64; ++k) acc += W1[u * 64 + k] * V1[k * 32 + w];
        g_M1[t2] = acc * (1.0f / sqrtf(96.0f * 64.0f));
    }
}

// ---------------------------------------------------------------------------
// Kernel 2: per-node precompute
//   R[c]   = sum_u s[u]   * M0[u,c]           (c<64)
//   U[c,i] = sum_u v[u,i] * M0[64+u,c]        (1/sqrt3 already folded)
//   P[w]   = sum_u s[u]   * M1[u,w]           (w<32)
//   Q[w,i] = sum_u v[u,i] * M1[64+u,w]
// Layout per node: [ (R,U0,U1,U2) x 64 | (P,Q0,Q1,Q2) x 32 ]  -> 384 floats
// ---------------------------------------------------------------------------
#define NODES_PER_BLOCK 16
__global__ void node_pre(const float* __restrict__ nf) {
    __shared__ float sM0[96 * 64];
    __shared__ float sM1[96 * 32];
    __shared__ float sf[160];
    int tid = threadIdx.x;  // 128 threads
    for (int i = tid; i < 96 * 64; i += 128) sM0[i] = g_M0[i];
    for (int i = tid; i < 96 * 32; i += 128) sM1[i] = g_M1[i];
    int n0 = blockIdx.x * NODES_PER_BLOCK;
    for (int nn = 0; nn < NODES_PER_BLOCK; ++nn) {
        int n = n0 + nn;
        if (n >= N_NODES) break;
        __syncthreads();                       // covers sM load (iter0) / prior compute
        for (int i = tid; i < 160; i += 128) sf[i] = nf[(size_t)n * 160 + i];
        __syncthreads();
        if (tid < 64) {
            int c = tid;
            float R = 0.f, U0 = 0.f, U1 = 0.f, U2 = 0.f;
            #pragma unroll
            for (int u = 0; u < 64; ++u) R += sf[u] * sM0[u * 64 + c];
            #pragma unroll
            for (int u = 0; u < 32; ++u) {
                float m = sM0[(64 + u) * 64 + c];
                U0 += sf[64 + 3 * u + 0] * m;
                U1 += sf[64 + 3 * u + 1] * m;
                U2 += sf[64 + 3 * u + 2] * m;
            }
            float* o = g_pre + (size_t)n * PRE + 4 * c;
            o[0] = R; o[1] = U0; o[2] = U1; o[3] = U2;
        } else if (tid < 96) {
            int w = tid - 64;
            float P = 0.f, Q0 = 0.f, Q1 = 0.f, Q2 = 0.f;
            #pragma unroll
            for (int u = 0; u < 64; ++u) P += sf[u] * sM1[u * 32 + w];
            #pragma unroll
            for (int u = 0; u < 32; ++u) {
                float m = sM1[(64 + u) * 32 + w];
                Q0 += sf[64 + 3 * u + 0] * m;
                Q1 += sf[64 + 3 * u + 1] * m;
                Q2 += sf[64 + 3 * u + 2] * m;
            }
            float* o = g_pre + (size_t)n * PRE + 256 + 4 * w;
            o[0] = P; o[1] = Q0; o[2] = Q1; o[3] = Q2;
        }
    }
}

// ---------------------------------------------------------------------------
// Kernel 3: edge scatter.  320 threads/block = 8 edges x 40-thread groups.
// Thread j of a group owns 4 contiguous output channels -> one red.v4 each.
//   channels [0,64):   msg[c] = e0*R[c] + e1.U[c]
//   channels [64,160): k = c-64, w=k/3, i=k%3: msg = e1[i]*P[w] + e0*Q[w,i]
// ---------------------------------------------------------------------------
__device__ __forceinline__ void red_v4(float* p, float a, float b, float c, float d) {
    asm volatile("red.global.add.v4.f32 [%0], {%1, %2, %3, %4};"
                 :: "l"(p), "f"(a), "f"(b), "f"(c), "f"(d) : "memory");
}
__device__ __forceinline__ float sel3(float a, float b, float c, int i) {
    return (i == 0) ? a : ((i == 1) ? b : c);
}

#define EPB 8
__global__ __launch_bounds__(320) void edge_kernel(const int* __restrict__ ei,
                                                   const float* __restrict__ ea,
                                                   float* __restrict__ out) {
    __shared__ int    s_src[EPB];
    __shared__ int    s_dst[EPB];
    __shared__ float4 s_attr[EPB];
    int tid = threadIdx.x;
    int ebase = blockIdx.x * EPB;
    if (tid < EPB) {
        int e = ebase + tid;
        s_src[tid]  = ei[e];
        s_dst[tid]  = ei[N_EDGES + e];
        s_attr[tid] = ((const float4*)ea)[e];
    }
    __syncthreads();

    int g = tid / 40;
    int j = tid - g * 40;
    const float* base = g_pre + (size_t)s_src[g] * PRE;
    float*       ob   = out + (size_t)s_dst[g] * 160;
    float4 A  = s_attr[g];
    float  e0 = A.x, ex = A.y, ey = A.z, ez = A.w;

    if (j < 16) {
        int c0 = 4 * j;
        const float4* bp = (const float4*)base + c0;
        float4 k0 = bp[0], k1 = bp[1], k2 = bp[2], k3 = bp[3];
        float v0 = e0 * k0.x + ex * k0.y + ey * k0.z + ez * k0.w;
        float v1 = e0 * k1.x + ex * k1.y + ey * k1.z + ez * k1.w;
        float v2 = e0 * k2.x + ex * k2.y + ey * k2.z + ez * k2.w;
        float v3 = e0 * k3.x + ex * k3.y + ey * k3.z + ez * k3.w;
        red_v4(ob + c0, v0, v1, v2, v3);
    } else {
        int kk = 4 * (j - 16);           // 0..92, flat index into the 96 o1 channels
        int w0 = kk / 3;                 // <= 30, so w0+1 <= 31 always valid
        int i0 = kk - 3 * w0;            // 0..2
        const float4* bp = (const float4*)(base + 256);
        float4 p0 = bp[w0], p1 = bp[w0 + 1];
        float v[4];
        #pragma unroll
        for (int t = 0; t < 4; ++t) {
            int  loc = i0 + t;           // 0..5
            bool hi  = (loc >= 3);
            int  i   = hi ? loc - 3 : loc;
            float P  = hi ? p1.x : p0.x;
            float Q  = hi ? sel3(p1.y, p1.z, p1.w, i) : sel3(p0.y, p0.z, p0.w, i);
            v[t] = sel3(ex, ey, ez, i) * P + e0 * Q;
        }
        red_v4(ob + 64 + kk, v[0], v[1], v[2], v[3]);
    }
}

// ---------------------------------------------------------------------------
// Kernel 4: warp-per-node LayerNorm (in-place), 160 channels, eps=1e-5
// ---------------------------------------------------------------------------
__global__ void ln_kernel(float* __restrict__ out, const float* __restrict__ gamma,
                          const float* __restrict__ beta) {
    int warp = (blockIdx.x * blockDim.x + threadIdx.x) >> 5;
    int lane = threadIdx.x & 31;
    if (warp >= N_NODES) return;
    float* row = out + (size_t)warp * 160;
    float x[5];
    float s = 0.f;
    #pragma unroll
    for (int k = 0; k < 5; ++k) { x[k] = row[lane + 32 * k]; s += x[k]; }
    #pragma unroll
    for (int o = 16; o > 0; o >>= 1) s += __shfl_xor_sync(0xFFFFFFFFu, s, o);
    float mu = s * (1.0f / 160.0f);
    float vs = 0.f;
    #pragma unroll
    for (int k = 0; k < 5; ++k) { float d = x[k] - mu; vs += d * d; }
    #pragma unroll
    for (int o = 16; o > 0; o >>= 1) vs += __shfl_xor_sync(0xFFFFFFFFu, vs, o);
    float r = rsqrtf(vs * (1.0f / 160.0f) + 1e-5f);
    #pragma unroll
    for (int k = 0; k < 5; ++k) {
        int c = lane + 32 * k;
        row[c] = (x[k] - mu) * r * gamma[c] + beta[c];
    }
}

// ---------------------------------------------------------------------------
extern "C" void kernel_launch(void* const* d_in, const int* in_sizes, int n_in,
                              void* d_out, int out_size) {
    const float* nf    = (const float*)d_in[0];   // node_features (20000,160)
    const int*   ei    = (const int*)  d_in[1];   // edge_index (2,320000)
    const float* ea    = (const float*)d_in[2];   // edge_attr (320000,4)
    const float* W0    = (const float*)d_in[4];   // (96,128)
    const float* W1    = (const float*)d_in[5];   // (96,64)
    const float* V0    = (const float*)d_in[8];   // (128,64)
    const float* V1    = (const float*)d_in[9];   // (64,32)
    const float* gamma = (const float*)d_in[10];  // (160,)
    const float* beta  = (const float*)d_in[11];  // (160,)
    float* out = (float*)d_out;                   // (20000,160) fp32

    int n4 = (N_NODES * 160) / 4;                 // 800000
    zero_kernel<<<(n4 + 255) / 256, 256>>>((float4*)out, n4);
    build_M<<<(96 * 64 + 96 * 32 + 255) / 256, 256>>>(W0, W1, V0, V1);
    node_pre<<<(N_NODES + NODES_PER_BLOCK - 1) / NODES_PER_BLOCK, 128>>>(nf);
    edge_kernel<<<N_EDGES / EPB, 320>>>(ei, ea, out);
    ln_kernel<<<(N_NODES * 32 + 255) / 256, 256>>>(out, gamma, beta);
}

// round 2
// speedup vs baseline: 1.2422x; 1.2422x over previous
#include <cuda_runtime.h>
#include <math.h>

#define N_NODES 20000
#define N_EDGES 320000
#define D_IN    160
#define PRE     384   // planar per-node: R[64]|U0[64]|U1[64]|U2[64]|P[32]|Q0[32]|Q1[32]|Q2[32]

__device__ float g_M0[96 * 64];
__device__ float g_M1[96 * 32];
__device__ float g_pre[(size_t)N_NODES * PRE];  // ~30.7 MB, L2-resident

// ---------------------------------------------------------------------------
__global__ void zero_kernel(float4* __restrict__ out, int n4) {
    int i = blockIdx.x * blockDim.x + threadIdx.x;
    if (i < n4) out[i] = make_float4(0.f, 0.f, 0.f, 0.f);
}

// ---------------------------------------------------------------------------
__global__ void build_M(const float* __restrict__ W0, const float* __restrict__ W1,
                        const float* __restrict__ V0, const float* __restrict__ V1) {
    int t = blockIdx.x * blockDim.x + threadIdx.x;
    if (t < 96 * 64) {
        int u = t >> 6, c = t & 63;
        float acc = 0.f;
        #pragma unroll 8
        for (int k = 0; k < 128; ++k) acc += W0[u * 128 + k] * V0[k * 64 + c];
        float s = 1.0f / sqrtf(96.0f * 128.0f);
        if (u >= 64) s *= 0.5773502691896258f;   // fold 1/sqrt(3)
        g_M0[t] = acc * s;
    } else if (t < 96 * 64 + 96 * 32) {
        int t2 = t - 96 * 64;
        int u = t2 >> 5, w = t2 & 31;
        float acc = 0.f;
        #pragma unroll 8
        for (int k = 0; k < 64; ++k) acc += W1[u * 64 + k] * V1[k * 32 + w];
        g_M1[t2] = acc * (1.0f / sqrtf(96.0f * 64.0f));
    }
}

// ---------------------------------------------------------------------------
// Per-node precompute, PLANAR output layout.
// ---------------------------------------------------------------------------
#define NODES_PER_BLOCK 16
__global__ void node_pre(const float* __restrict__ nf) {
    __shared__ float sM0[96 * 64];
    __shared__ float sM1[96 * 32];
    __shared__ float sf[160];
    int tid = threadIdx.x;  // 128 threads
    for (int i = tid; i < 96 * 64; i += 128) sM0[i] = g_M0[i];
    for (int i = tid; i < 96 * 32; i += 128) sM1[i] = g_M1[i];
    int n0 = blockIdx.x * NODES_PER_BLOCK;
    for (int nn = 0; nn < NODES_PER_BLOCK; ++nn) {
        int n = n0 + nn;
        if (n >= N_NODES) break;
        __syncthreads();
        for (int i = tid; i < 160; i += 128) sf[i] = nf[(size_t)n * 160 + i];
        __syncthreads();
        float* pb = g_pre + (size_t)n * PRE;
        if (tid < 64) {
            int c = tid;
            float R = 0.f, U0 = 0.f, U1 = 0.f, U2 = 0.f;
            #pragma unroll
            for (int u = 0; u < 64; ++u) R += sf[u] * sM0[u * 64 + c];
            #pragma unroll
            for (int u = 0; u < 32; ++u) {
                float m = sM0[(64 + u) * 64 + c];
                U0 += sf[64 + 3 * u + 0] * m;
                U1 += sf[64 + 3 * u + 1] * m;
                U2 += sf[64 + 3 * u + 2] * m;
            }
            pb[c] = R; pb[64 + c] = U0; pb[128 + c] = U1; pb[192 + c] = U2;
        } else if (tid < 96) {
            int w = tid - 64;
            float P = 0.f, Q0 = 0.f, Q1 = 0.f, Q2 = 0.f;
            #pragma unroll
            for (int u = 0; u < 64; ++u) P += sf[u] * sM1[u * 32 + w];
            #pragma unroll
            for (int u = 0; u < 32; ++u) {
                float m = sM1[(64 + u) * 32 + w];
                Q0 += sf[64 + 3 * u + 0] * m;
                Q1 += sf[64 + 3 * u + 1] * m;
                Q2 += sf[64 + 3 * u + 2] * m;
            }
            pb[256 + w] = P; pb[288 + w] = Q0; pb[320 + w] = Q1; pb[352 + w] = Q2;
        }
    }
}

// ---------------------------------------------------------------------------
// Edge scatter: 24-thread groups (16 o0 lanes + 8 o1 lanes), planar loads.
//   o0 lane j (<16):  channels 4j..4j+3
//       v_t = e0*R[4j+t] + ex*U0[4j+t] + ey*U1[4j+t] + ez*U2[4j+t]
//   o1 lane jj (=j-16, <8): w = 4jj..4jj+3, channels 64+12jj .. 64+12jj+11
//       m(w,i) = e1[i]*P[w] + e0*Qi[w]
// All loads fully coalesced float4 within the lane subset. 40 red.v4/edge.
// ---------------------------------------------------------------------------
__device__ __forceinline__ void red_v4(float* p, float a, float b, float c, float d) {
    asm volatile("red.global.add.v4.f32 [%0], {%1, %2, %3, %4};"
                 :: "l"(p), "f"(a), "f"(b), "f"(c), "f"(d) : "memory");
}

#define EPB 16
#define TPE 24
__global__ __launch_bounds__(EPB * TPE) void edge_kernel(const int* __restrict__ ei,
                                                         const float* __restrict__ ea,
                                                         float* __restrict__ out) {
    __shared__ int    s_src[EPB];
    __shared__ int    s_dst[EPB];
    __shared__ float4 s_attr[EPB];
    int tid = threadIdx.x;
    int ebase = blockIdx.x * EPB;
    if (tid < EPB) {
        int e = ebase + tid;
        s_src[tid]  = ei[e];
        s_dst[tid]  = ei[N_EDGES + e];
        s_attr[tid] = ((const float4*)ea)[e];
    }
    __syncthreads();

    int g = tid / TPE;
    int j = tid - g * TPE;
    const float4* bp = (const float4*)(g_pre + (size_t)s_src[g] * PRE);
    float*        ob = out + (size_t)s_dst[g] * 160;
    float4 A  = s_attr[g];
    float  e0 = A.x, ex = A.y, ey = A.z, ez = A.w;

    if (j < 16) {
        float4 R  = bp[j];
        float4 U0 = bp[16 + j];
        float4 U1 = bp[32 + j];
        float4 U2 = bp[48 + j];
        red_v4(ob + 4 * j,
               e0 * R.x + ex * U0.x + ey * U1.x + ez * U2.x,
               e0 * R.y + ex * U0.y + ey * U1.y + ez * U2.y,
               e0 * R.z + ex * U0.z + ey * U1.z + ez * U2.z,
               e0 * R.w + ex * U0.w + ey * U1.w + ez * U2.w);
    } else {
        int jj = j - 16;                       // 0..7
        float4 P  = bp[64 + jj];
        float4 Q0 = bp[72 + jj];
        float4 Q1 = bp[80 + jj];
        float4 Q2 = bp[88 + jj];
        float* o = ob + 64 + 12 * jj;
        red_v4(o,     ex * P.x + e0 * Q0.x,  ey * P.x + e0 * Q1.x,
                      ez * P.x + e0 * Q2.x,  ex * P.y + e0 * Q0.y);
        red_v4(o + 4, ey * P.y + e0 * Q1.y,  ez * P.y + e0 * Q2.y,
                      ex * P.z + e0 * Q0.z,  ey * P.z + e0 * Q1.z);
        red_v4(o + 8, ez * P.z + e0 * Q2.z,  ex * P.w + e0 * Q0.w,
                      ey * P.w + e0 * Q1.w,  ez * P.w + e0 * Q2.w);
    }
}

// ---------------------------------------------------------------------------
__global__ void ln_kernel(float* __restrict__ out, const float* __restrict__ gamma,
                          const float* __restrict__ beta) {
    int warp = (blockIdx.x * blockDim.x + threadIdx.x) >> 5;
    int lane = threadIdx.x & 31;
    if (warp >= N_NODES) return;
    float* row = out + (size_t)warp * 160;
    float x[5];
    float s = 0.f;
    #pragma unroll
    for (int k = 0; k < 5; ++k) { x[k] = row[lane + 32 * k]; s += x[k]; }
    #pragma unroll
    for (int o = 16; o > 0; o >>= 1) s += __shfl_xor_sync(0xFFFFFFFFu, s, o);
    float mu = s * (1.0f / 160.0f);
    float vs = 0.f;
    #pragma unroll
    for (int k = 0; k < 5; ++k) { float d = x[k] - mu; vs += d * d; }
    #pragma unroll
    for (int o = 16; o > 0; o >>= 1) vs += __shfl_xor_sync(0xFFFFFFFFu, vs, o);
    float r = rsqrtf(vs * (1.0f / 160.0f) + 1e-5f);
    #pragma unroll
    for (int k = 0; k < 5; ++k) {
        int c = lane + 32 * k;
        row[c] = (x[k] - mu) * r * gamma[c] + beta[c];
    }
}

// ---------------------------------------------------------------------------
extern "C" void kernel_launch(void* const* d_in, const int* in_sizes, int n_in,
                              void* d_out, int out_size) {
    const float* nf    = (const float*)d_in[0];
    const int*   ei    = (const int*)  d_in[1];
    const float* ea    = (const float*)d_in[2];
    const float* W0    = (const float*)d_in[4];
    const float* W1    = (const float*)d_in[5];
    const float* V0    = (const float*)d_in[8];
    const float* V1    = (const float*)d_in[9];
    const float* gamma = (const float*)d_in[10];
    const float* beta  = (const float*)d_in[11];
    float* out = (float*)d_out;

    int n4 = (N_NODES * 160) / 4;
    zero_kernel<<<(n4 + 255) / 256, 256>>>((float4*)out, n4);
    build_M<<<(96 * 64 + 96 * 32 + 255) / 256, 256>>>(W0, W1, V0, V1);
    node_pre<<<(N_NODES + NODES_PER_BLOCK - 1) / NODES_PER_BLOCK, 128>>>(nf);
    edge_kernel<<<N_EDGES / EPB, EPB * TPE>>>(ei, ea, out);
    ln_kernel<<<(N_NODES * 32 + 255) / 256, 256>>>(out, gamma, beta);
}

// round 3
// speedup vs baseline: 1.3718x; 1.1043x over previous
#include <cuda_runtime.h>
#include <math.h>

#define N_NODES 20000
#define N_EDGES 320000
#define PRE     384   // planar: R[64]|U0[64]|U1[64]|U2[64]|P[32]|Q0[32]|Q1[32]|Q2[32]

__device__ float g_M0[96 * 64];
__device__ float g_M1[96 * 32];
__device__ float g_pre[(size_t)N_NODES * PRE];   // ~30.7 MB

// CSR scratch
__device__ int    g_count[N_NODES];
__device__ int    g_cursor[N_NODES];
__device__ int    g_off[N_NODES + 1];
__device__ int    g_psrc[N_EDGES];
__device__ float4 g_pattr[N_EDGES];

// ---------------------------------------------------------------------------
__global__ void zero_cnt() {
    int i = blockIdx.x * blockDim.x + threadIdx.x;
    if (i < N_NODES) { g_count[i] = 0; g_cursor[i] = 0; }
}

// ---------------------------------------------------------------------------
__global__ void build_M(const float* __restrict__ W0, const float* __restrict__ W1,
                        const float* __restrict__ V0, const float* __restrict__ V1) {
    int t = blockIdx.x * blockDim.x + threadIdx.x;
    if (t < 96 * 64) {
        int u = t >> 6, c = t & 63;
        float acc = 0.f;
        #pragma unroll 8
        for (int k = 0; k < 128; ++k) acc += W0[u * 128 + k] * V0[k * 64 + c];
        float s = 1.0f / sqrtf(96.0f * 128.0f);
        if (u >= 64) s *= 0.5773502691896258f;   // fold 1/sqrt(3)
        g_M0[t] = acc * s;
    } else if (t < 96 * 64 + 96 * 32) {
        int t2 = t - 96 * 64;
        int u = t2 >> 5, w = t2 & 31;
        float acc = 0.f;
        #pragma unroll 8
        for (int k = 0; k < 64; ++k) acc += W1[u * 64 + k] * V1[k * 32 + w];
        g_M1[t2] = acc * (1.0f / sqrtf(96.0f * 64.0f));
    }
}

// ---------------------------------------------------------------------------
__global__ void hist_kernel(const int* __restrict__ ei) {
    int e = blockIdx.x * blockDim.x + threadIdx.x;
    if (e < N_EDGES) atomicAdd(&g_count[ei[N_EDGES + e]], 1);
}

// Single-block exclusive scan of g_count -> g_off (1024 threads x 20 items)
__global__ void scan_kernel() {
    __shared__ int wsum[32];
    int t = threadIdx.x;
    int base = t * 20;
    int v[20];
    int s = 0;
    #pragma unroll
    for (int j = 0; j < 20; ++j) {
        int i = base + j;
        int c = (i < N_NODES) ? g_count[i] : 0;
        v[j] = s; s += c;
    }
    int lane = t & 31, wid = t >> 5;
    int x = s;
    #pragma unroll
    for (int o = 1; o < 32; o <<= 1) {
        int y = __shfl_up_sync(0xFFFFFFFFu, x, o);
        if (lane >= o) x += y;
    }
    if (lane == 31) wsum[wid] = x;
    __syncthreads();
    if (wid == 0) {
        int y = wsum[lane];
        #pragma unroll
        for (int o = 1; o < 32; o <<= 1) {
            int z = __shfl_up_sync(0xFFFFFFFFu, y, o);
            if (lane >= o) y += z;
        }
        wsum[lane] = y;
    }
    __syncthreads();
    int excl = x - s + (wid > 0 ? wsum[wid - 1] : 0);
    #pragma unroll
    for (int j = 0; j < 20; ++j) {
        int i = base + j;
        if (i < N_NODES) g_off[i] = excl + v[j];
    }
    if (t == 1023) g_off[N_NODES] = excl + s;
}

__global__ void scatter_kernel(const int* __restrict__ ei, const float* __restrict__ ea) {
    int e = blockIdx.x * blockDim.x + threadIdx.x;
    if (e >= N_EDGES) return;
    int src = ei[e];
    int dst = ei[N_EDGES + e];
    float4 a = ((const float4*)ea)[e];
    int pos = atomicAdd(&g_cursor[dst], 1);
    int idx = g_off[dst] + pos;
    g_psrc[idx]  = src;
    g_pattr[idx] = a;
}

// ---------------------------------------------------------------------------
// node_pre: register-tiled (4 nodes x 4 cols). Block = 384 thr, 16 nodes.
//  warps 0-2  (t<96) : s-driven planes R (64 cols), P (32 cols), u = 0..63
//  warps 3-11 (t>=96): v-driven planes U0..U2 (192), Q0..Q2 (96), u = 0..31
// ---------------------------------------------------------------------------
#define NT 16
__global__ __launch_bounds__(384) void node_pre(const float* __restrict__ nf) {
    __shared__ float sM0[96 * 64];
    __shared__ float sM1[96 * 32];
    __shared__ float sfT[160 * 17];      // transposed features, pad 17
    int t = threadIdx.x;
    for (int i = t; i < 96 * 64; i += 384) sM0[i] = g_M0[i];
    for (int i = t; i < 96 * 32; i += 384) sM1[i] = g_M1[i];
    int n0 = blockIdx.x * NT;
    for (int i = t; i < NT * 160; i += 384) {
        int n = i / 160, ch = i % 160;
        sfT[ch * 17 + n] = nf[(size_t)(n0 + n) * 160 + ch];
    }
    __syncthreads();

    const float* mbase;
    const float* sfb;
    int mstride, sfstep, uiters, outoff, ng;

    if (t < 96) {
        int g = t / 24, h = t % 24;
        ng = g; uiters = 64; sfstep = 17;
        if (h < 16) { mbase = sM0 + 4 * h;        mstride = 64; outoff = 4 * h; }
        else        { mbase = sM1 + 4 * (h - 16); mstride = 32; outoff = 256 + 4 * (h - 16); }
        sfb = sfT + 4 * g;
    } else {
        int idx = t - 96;
        int g = idx / 72, h = idx % 72;
        ng = g; uiters = 32; sfstep = 3 * 17;
        int i;
        if (h < 48) {
            i = h / 16; int cw = (h % 16) * 4;
            mbase = sM0 + 64 * 64 + cw; mstride = 64; outoff = 64 + 64 * i + cw;
        } else {
            int h2 = h - 48; i = h2 / 8; int w0 = (h2 % 8) * 4;
            mbase = sM1 + 64 * 32 + w0; mstride = 32; outoff = 288 + 32 * i + w0;
        }
        sfb = sfT + (64 + i) * 17 + 4 * g;
    }

    float a0x = 0.f, a0y = 0.f, a0z = 0.f, a0w = 0.f;
    float a1x = 0.f, a1y = 0.f, a1z = 0.f, a1w = 0.f;
    float a2x = 0.f, a2y = 0.f, a2z = 0.f, a2w = 0.f;
    float a3x = 0.f, a3y = 0.f, a3z = 0.f, a3w = 0.f;

    for (int u = 0; u < uiters; ++u) {
        float4 m = *(const float4*)(mbase + u * mstride);
        const float* sp = sfb + u * sfstep;
        float s0 = sp[0], s1 = sp[1], s2 = sp[2], s3 = sp[3];
        a0x += m.x * s0; a0y += m.y * s0; a0z += m.z * s0; a0w += m.w * s0;
        a1x += m.x * s1; a1y += m.y * s1; a1z += m.z * s1; a1w += m.w * s1;
        a2x += m.x * s2; a2y += m.y * s2; a2z += m.z * s2; a2w += m.w * s2;
        a3x += m.x * s3; a3y += m.y * s3; a3z += m.z * s3; a3w += m.w * s3;
    }

    size_t nb = (size_t)(n0 + 4 * ng) * PRE + outoff;
    *(float4*)(g_pre + nb)             = make_float4(a0x, a0y, a0z, a0w);
    *(float4*)(g_pre + nb + PRE)       = make_float4(a1x, a1y, a1z, a1w);
    *(float4*)(g_pre + nb + 2 * PRE)   = make_float4(a2x, a2y, a2z, a2w);
    *(float4*)(g_pre + nb + 3 * PRE)   = make_float4(a3x, a3y, a3z, a3w);
}

// ---------------------------------------------------------------------------
// Gather + fused LayerNorm. Warp per node. Lane l owns channels:
//   o0: 2l, 2l+1     (float2 loads from R/U planes)
//   o1: 64+3l..64+3l+2  via P[l], Q0[l], Q1[l], Q2[l]
// ---------------------------------------------------------------------------
__global__ __launch_bounds__(256) void gather_ln(float* __restrict__ out,
                                                 const float* __restrict__ gamma,
                                                 const float* __restrict__ beta) {
    int node = blockIdx.x * 8 + (threadIdx.x >> 5);
    int lane = threadIdx.x & 31;
    if (node >= N_NODES) return;
    int beg = g_off[node], end = g_off[node + 1];

    float ax = 0.f, ay = 0.f, c0 = 0.f, c1 = 0.f, c2 = 0.f;

    for (int k = beg; k < end; k += 32) {
        int rem = end - k;
        int    msrc  = 0;
        float4 mattr = make_float4(0.f, 0.f, 0.f, 0.f);
        if (lane < rem) { msrc = g_psrc[k + lane]; mattr = g_pattr[k + lane]; }
        int cnt = rem < 32 ? rem : 32;
        for (int b = 0; b < cnt; ++b) {
            int   src = __shfl_sync(0xFFFFFFFFu, msrc, b);
            float e0  = __shfl_sync(0xFFFFFFFFu, mattr.x, b);
            float ex  = __shfl_sync(0xFFFFFFFFu, mattr.y, b);
            float ey  = __shfl_sync(0xFFFFFFFFu, mattr.z, b);
            float ez  = __shfl_sync(0xFFFFFFFFu, mattr.w, b);
            const float* pb = g_pre + (size_t)src * PRE;
            float2 R  = ((const float2*)pb)[lane];
            float2 U0 = ((const float2*)(pb + 64))[lane];
            float2 U1 = ((const float2*)(pb + 128))[lane];
            float2 U2 = ((const float2*)(pb + 192))[lane];
            float  P  = pb[256 + lane];
            float  Q0 = pb[288 + lane];
            float  Q1 = pb[320 + lane];
            float  Q2 = pb[352 + lane];
            ax += e0 * R.x + ex * U0.x + ey * U1.x + ez * U2.x;
            ay += e0 * R.y + ex * U0.y + ey * U1.y + ez * U2.y;
            c0 += ex * P + e0 * Q0;
            c1 += ey * P + e0 * Q1;
            c2 += ez * P + e0 * Q2;
        }
    }

    // LayerNorm over 160 channels
    float s = ax + ay + c0 + c1 + c2;
    #pragma unroll
    for (int o = 16; o > 0; o >>= 1) s += __shfl_xor_sync(0xFFFFFFFFu, s, o);
    float mu = s * (1.0f / 160.0f);
    float dx = ax - mu, dy = ay - mu, d0 = c0 - mu, d1 = c1 - mu, d2 = c2 - mu;
    float vs = dx * dx + dy * dy + d0 * d0 + d1 * d1 + d2 * d2;
    #pragma unroll
    for (int o = 16; o > 0; o >>= 1) vs += __shfl_xor_sync(0xFFFFFFFFu, vs, o);
    float r = rsqrtf(vs * (1.0f / 160.0f) + 1e-5f);

    float* row = out + (size_t)node * 160;
    float2 gg = ((const float2*)gamma)[lane];
    float2 bb = ((const float2*)beta)[lane];
    float2 o0v = make_float2(dx * r * gg.x + bb.x, dy * r * gg.y + bb.y);
    ((float2*)row)[lane] = o0v;
    int cb = 64 + 3 * lane;
    row[cb + 0] = d0 * r * gamma[cb + 0] + beta[cb + 0];
    row[cb + 1] = d1 * r * gamma[cb + 1] + beta[cb + 1];
    row[cb + 2] = d2 * r * gamma[cb + 2] + beta[cb + 2];
}

// ---------------------------------------------------------------------------
extern "C" void kernel_launch(void* const* d_in, const int* in_sizes, int n_in,
                              void* d_out, int out_size) {
    const float* nf    = (const float*)d_in[0];
    const int*   ei    = (const int*)  d_in[1];
    const float* ea    = (const float*)d_in[2];
    const float* W0    = (const float*)d_in[4];
    const float* W1    = (const float*)d_in[5];
    const float* V0    = (const float*)d_in[8];
    const float* V1    = (const float*)d_in[9];
    const float* gamma = (const float*)d_in[10];
    const float* beta  = (const float*)d_in[11];
    float* out = (float*)d_out;

    zero_cnt<<<(N_NODES + 255) / 256, 256>>>();
    build_M<<<(96 * 64 + 96 * 32 + 255) / 256, 256>>>(W0, W1, V0, V1);
    hist_kernel<<<(N_EDGES + 255) / 256, 256>>>(ei);
    scan_kernel<<<1, 1024>>>();
    scatter_kernel<<<(N_EDGES + 255) / 256, 256>>>(ei, ea);
    node_pre<<<N_NODES / NT, 384>>>(nf);
    gather_ln<<<(N_NODES + 7) / 8, 256>>>(out, gamma, beta);
}

// round 4
// speedup vs baseline: 1.4019x; 1.0219x over previous
#include <cuda_runtime.h>
#include <cuda_fp16.h>
#include <math.h>

#define N_NODES 20000
#define N_EDGES 320000
#define CAP     96      // bucket capacity per node (Poisson(16); P(deg>=96) ~ 1e-60)

__device__ float  g_M0[96 * 64];
__device__ float  g_M1[96 * 32];
// fp16 precompute, interleaved: per node 384 halves (768B):
//   [0,256):  group c (c<64) at 4c:   {R[c], U0[c], U1[c], U2[c]}
//   [256,384): group w (w<32) at 256+4w: {P[w], Q0[w], Q1[w], Q2[w]}
__device__ __half g_preh[(size_t)N_NODES * 384];   // ~15.4 MB
__device__ int    g_cursor[N_NODES];
__device__ int    g_psrc[(size_t)N_NODES * CAP];
__device__ float4 g_pattr[(size_t)N_NODES * CAP];

// ---------------------------------------------------------------------------
// Fused init: build M0/M1 and zero cursors in one launch
// ---------------------------------------------------------------------------
__global__ void init_kernel(const float* __restrict__ W0, const float* __restrict__ W1,
                            const float* __restrict__ V0, const float* __restrict__ V1) {
    int t = blockIdx.x * blockDim.x + threadIdx.x;
    if (t < 96 * 64) {
        int u = t >> 6, c = t & 63;
        float acc = 0.f;
        #pragma unroll 8
        for (int k = 0; k < 128; ++k) acc += W0[u * 128 + k] * V0[k * 64 + c];
        float s = 1.0f / sqrtf(96.0f * 128.0f);
        if (u >= 64) s *= 0.5773502691896258f;   // fold 1/sqrt(3)
        g_M0[t] = acc * s;
    } else if (t < 96 * 64 + 96 * 32) {
        int t2 = t - 96 * 64;
        int u = t2 >> 5, w = t2 & 31;
        float acc = 0.f;
        #pragma unroll 8
        for (int k = 0; k < 64; ++k) acc += W1[u * 64 + k] * V1[k * 32 + w];
        g_M1[t2] = acc * (1.0f / sqrtf(96.0f * 64.0f));
    } else if (t < 96 * 64 + 96 * 32 + N_NODES) {
        g_cursor[t - 96 * 64 - 96 * 32] = 0;
    }
}

// ---------------------------------------------------------------------------
// Scatter into fixed-capacity buckets (no hist/scan needed)
// ---------------------------------------------------------------------------
__global__ void scatter_kernel(const int* __restrict__ ei, const float* __restrict__ ea) {
    int e = blockIdx.x * blockDim.x + threadIdx.x;
    if (e >= N_EDGES) return;
    int src = ei[e];
    int dst = ei[N_EDGES + e];
    float4 a = ((const float4*)ea)[e];
    int pos = atomicAdd(&g_cursor[dst], 1);
    size_t idx = (size_t)dst * CAP + pos;
    g_psrc[idx]  = src;
    g_pattr[idx] = a;
}

// ---------------------------------------------------------------------------
// node_pre: thread-per-channel-group. Block = 384 thr = 4 nodes x 96 threads.
//   h < 64 : channel c -> {R,U0,U1,U2}, 160 FMA
//   h >= 64: w = h-64  -> {P,Q0,Q1,Q2}, 160 FMA
// Writes one uint2 (4 halves) per thread, coalesced.
// ---------------------------------------------------------------------------
#define NPB 4
__global__ __launch_bounds__(384) void node_pre(const float* __restrict__ nf) {
    __shared__ float sM0[96 * 64];
    __shared__ float sM1[96 * 32];
    __shared__ float sf[NPB * 160];
    int t = threadIdx.x;
    for (int i = t; i < 96 * 64; i += 384) sM0[i] = g_M0[i];
    for (int i = t; i < 96 * 32; i += 384) sM1[i] = g_M1[i];
    int n0 = blockIdx.x * NPB;
    for (int i = t; i < NPB * 160; i += 384) sf[i] = nf[(size_t)n0 * 160 + i];
    __syncthreads();

    int sub = t / 96, h = t - sub * 96;
    int n = n0 + sub;
    const float* f = sf + sub * 160;

    if (h < 64) {
        int c = h;
        float R = 0.f, U0 = 0.f, U1 = 0.f, U2 = 0.f;
        #pragma unroll
        for (int u = 0; u < 64; ++u) R += f[u] * sM0[u * 64 + c];
        #pragma unroll
        for (int u = 0; u < 32; ++u) {
            float m = sM0[(64 + u) * 64 + c];
            U0 += f[64 + 3 * u + 0] * m;
            U1 += f[64 + 3 * u + 1] * m;
            U2 += f[64 + 3 * u + 2] * m;
        }
        __half2 h0 = __floats2half2_rn(R, U0);
        __half2 h1 = __floats2half2_rn(U1, U2);
        uint2 v;
        v.x = *(unsigned*)&h0; v.y = *(unsigned*)&h1;
        *(uint2*)(g_preh + (size_t)n * 384 + 4 * c) = v;
    } else {
        int w = h - 64;
        float P = 0.f, Q0 = 0.f, Q1 = 0.f, Q2 = 0.f;
        #pragma unroll
        for (int u = 0; u < 64; ++u) P += f[u] * sM1[u * 32 + w];
        #pragma unroll
        for (int u = 0; u < 32; ++u) {
            float m = sM1[(64 + u) * 32 + w];
            Q0 += f[64 + 3 * u + 0] * m;
            Q1 += f[64 + 3 * u + 1] * m;
            Q2 += f[64 + 3 * u + 2] * m;
        }
        __half2 h0 = __floats2half2_rn(P, Q0);
        __half2 h1 = __floats2half2_rn(Q1, Q2);
        uint2 v;
        v.x = *(unsigned*)&h0; v.y = *(unsigned*)&h1;
        *(uint2*)(g_preh + (size_t)n * 384 + 256 + 4 * w) = v;
    }
}

// ---------------------------------------------------------------------------
// Gather + fused LayerNorm. Warp per node.
//   lane l: o0 channels 2l,2l+1 via groups 2l,2l+1 (one LDG.128)
//           o1 channels 64+3l..+2 via group l of small region (one LDG.64)
// ---------------------------------------------------------------------------
__global__ __launch_bounds__(256) void gather_ln(float* __restrict__ out,
                                                 const float* __restrict__ gamma,
                                                 const float* __restrict__ beta) {
    int node = blockIdx.x * 8 + (threadIdx.x >> 5);
    int lane = threadIdx.x & 31;
    if (node >= N_NODES) return;
    int cnt = g_cursor[node];
    size_t bbase = (size_t)node * CAP;

    float ax = 0.f, ay = 0.f, c0 = 0.f, c1 = 0.f, c2 = 0.f;

    for (int k = 0; k < cnt; k += 32) {
        int rem = cnt - k;
        int    msrc  = 0;
        float4 mattr = make_float4(0.f, 0.f, 0.f, 0.f);
        if (lane < rem) { msrc = g_psrc[bbase + k + lane]; mattr = g_pattr[bbase + k + lane]; }
        int inner = rem < 32 ? rem : 32;
        for (int b = 0; b < inner; ++b) {
            int   src = __shfl_sync(0xFFFFFFFFu, msrc, b);
            float e0  = __shfl_sync(0xFFFFFFFFu, mattr.x, b);
            float ex  = __shfl_sync(0xFFFFFFFFu, mattr.y, b);
            float ey  = __shfl_sync(0xFFFFFFFFu, mattr.z, b);
            float ez  = __shfl_sync(0xFFFFFFFFu, mattr.w, b);
            const __half* pb = g_preh + (size_t)src * 384;
            uint4 bg = *(const uint4*)(pb + 8 * lane);        // groups 2l, 2l+1
            uint2 sm = *(const uint2*)(pb + 256 + 4 * lane);  // group l (small)
            float2 p0 = __half22float2(*(__half2*)&bg.x);     // R(2l),  U0(2l)
            float2 p1 = __half22float2(*(__half2*)&bg.y);     // U1(2l), U2(2l)
            float2 p2 = __half22float2(*(__half2*)&bg.z);     // R(2l+1),U0(2l+1)
            float2 p3 = __half22float2(*(__half2*)&bg.w);     // U1,U2 (2l+1)
            float2 s0 = __half22float2(*(__half2*)&sm.x);     // P(l), Q0(l)
            float2 s1 = __half22float2(*(__half2*)&sm.y);     // Q1(l), Q2(l)
            ax += e0 * p0.x + ex * p0.y + ey * p1.x + ez * p1.y;
            ay += e0 * p2.x + ex * p2.y + ey * p3.x + ez * p3.y;
            c0 += ex * s0.x + e0 * s0.y;
            c1 += ey * s0.x + e0 * s1.x;
            c2 += ez * s0.x + e0 * s1.y;
        }
    }

    // Fused LayerNorm over 160 channels
    float s = ax + ay + c0 + c1 + c2;
    #pragma unroll
    for (int o = 16; o > 0; o >>= 1) s += __shfl_xor_sync(0xFFFFFFFFu, s, o);
    float mu = s * (1.0f / 160.0f);
    float dx = ax - mu, dy = ay - mu, d0 = c0 - mu, d1 = c1 - mu, d2 = c2 - mu;
    float vs = dx * dx + dy * dy + d0 * d0 + d1 * d1 + d2 * d2;
    #pragma unroll
    for (int o = 16; o > 0; o >>= 1) vs += __shfl_xor_sync(0xFFFFFFFFu, vs, o);
    float r = rsqrtf(vs * (1.0f / 160.0f) + 1e-5f);

    float* row = out + (size_t)node * 160;
    float2 gg = ((const float2*)gamma)[lane];
    float2 bb = ((const float2*)beta)[lane];
    ((float2*)row)[lane] = make_float2(dx * r * gg.x + bb.x, dy * r * gg.y + bb.y);
    int cb = 64 + 3 * lane;
    row[cb + 0] = d0 * r * gamma[cb + 0] + beta[cb + 0];
    row[cb + 1] = d1 * r * gamma[cb + 1] + beta[cb + 1];
    row[cb + 2] = d2 * r * gamma[cb + 2] + beta[cb + 2];
}

// ---------------------------------------------------------------------------
extern "C" void kernel_launch(void* const* d_in, const int* in_sizes, int n_in,
                              void* d_out, int out_size) {
    const float* nf    = (const float*)d_in[0];
    const int*   ei    = (const int*)  d_in[1];
    const float* ea    = (const float*)d_in[2];
    const float* W0    = (const float*)d_in[4];
    const float* W1    = (const float*)d_in[5];
    const float* V0    = (const float*)d_in[8];
    const float* V1    = (const float*)d_in[9];
    const float* gamma = (const float*)d_in[10];
    const float* beta  = (const float*)d_in[11];
    float* out = (float*)d_out;

    int init_n = 96 * 64 + 96 * 32 + N_NODES;
    init_kernel<<<(init_n + 255) / 256, 256>>>(W0, W1, V0, V1);
    scatter_kernel<<<(N_EDGES + 255) / 256, 256>>>(ei, ea);
    node_pre<<<N_NODES / NPB, 384>>>(nf);
    gather_ln<<<(N_NODES + 7) / 8, 256>>>(out, gamma, beta);
}

// round 5
// speedup vs baseline: 1.7589x; 1.2547x over previous
#include <cuda_runtime.h>
#include <cuda_fp16.h>
#include <math.h>

#define N_NODES 20000
#define N_EDGES 320000
#define CAP     96      // bucket capacity per node (Poisson(16); P(deg>=96) ~ 1e-60)

__device__ float  g_M0[96 * 64];
__device__ float  g_M1[96 * 32];
// fp16 precompute, interleaved: per node 384 halves (768B):
//   [0,256):  group c (c<64) at 4c:   {R[c], U0[c], U1[c], U2[c]}
//   [256,384): group w (w<32) at 256+4w: {P[w], Q0[w], Q1[w], Q2[w]}
__device__ __half g_preh[(size_t)N_NODES * 384];   // ~15.4 MB
__device__ int    g_cursor[N_NODES];
__device__ int    g_psrc[(size_t)N_NODES * CAP];
__device__ float4 g_pattr[(size_t)N_NODES * CAP];

// ---------------------------------------------------------------------------
// Fused init: build M0/M1 and zero cursors in one launch
// ---------------------------------------------------------------------------
__global__ void init_kernel(const float* __restrict__ W0, const float* __restrict__ W1,
                            const float* __restrict__ V0, const float* __restrict__ V1) {
    int t = blockIdx.x * blockDim.x + threadIdx.x;
    if (t < 96 * 64) {
        int u = t >> 6, c = t & 63;
        float acc = 0.f;
        #pragma unroll 8
        for (int k = 0; k < 128; ++k) acc += W0[u * 128 + k] * V0[k * 64 + c];
        float s = 1.0f / sqrtf(96.0f * 128.0f);
        if (u >= 64) s *= 0.5773502691896258f;   // fold 1/sqrt(3)
        g_M0[t] = acc * s;
    } else if (t < 96 * 64 + 96 * 32) {
        int t2 = t - 96 * 64;
        int u = t2 >> 5, w = t2 & 31;
        float acc = 0.f;
        #pragma unroll 8
        for (int k = 0; k < 64; ++k) acc += W1[u * 64 + k] * V1[k * 32 + w];
        g_M1[t2] = acc * (1.0f / sqrtf(96.0f * 64.0f));
    } else if (t < 96 * 64 + 96 * 32 + N_NODES) {
        g_cursor[t - 96 * 64 - 96 * 32] = 0;
    }
}

// ---------------------------------------------------------------------------
// Scatter into fixed-capacity buckets
// ---------------------------------------------------------------------------
__global__ void scatter_kernel(const int* __restrict__ ei, const float* __restrict__ ea) {
    int e = blockIdx.x * blockDim.x + threadIdx.x;
    if (e >= N_EDGES) return;
    int src = ei[e];
    int dst = ei[N_EDGES + e];
    float4 a = ((const float4*)ea)[e];
    int pos = atomicAdd(&g_cursor[dst], 1);
    size_t idx = (size_t)dst * CAP + pos;
    g_psrc[idx]  = src;
    g_pattr[idx] = a;
}

// ---------------------------------------------------------------------------
// node_pre: block = 384 thr; 4 passes x 4 nodes = 16 nodes/block.
// M0/M1 loaded to smem ONCE per block (36KB), amortized over 16 nodes.
//   h < 64 : channel c -> {R,U0,U1,U2}
//   h >= 64: w = h-64  -> {P,Q0,Q1,Q2}
// ---------------------------------------------------------------------------
#define NPB 16
__global__ __launch_bounds__(384) void node_pre(const float* __restrict__ nf) {
    __shared__ float sM0[96 * 64];
    __shared__ float sM1[96 * 32];
    __shared__ float sf[4 * 160];
    int t = threadIdx.x;
    for (int i = t; i < 96 * 64; i += 384) sM0[i] = g_M0[i];
    for (int i = t; i < 96 * 32; i += 384) sM1[i] = g_M1[i];
    int nb = blockIdx.x * NPB;
    int sub = t / 96, h = t - sub * 96;

    for (int pass = 0; pass < NPB / 4; ++pass) {
        int n0 = nb + pass * 4;
        __syncthreads();
        for (int i = t; i < 4 * 160; i += 384) sf[i] = nf[(size_t)n0 * 160 + i];
        __syncthreads();

        int n = n0 + sub;
        const float* f = sf + sub * 160;

        if (h < 64) {
            int c = h;
            float R = 0.f, U0 = 0.f, U1 = 0.f, U2 = 0.f;
            #pragma unroll
            for (int u = 0; u < 64; ++u) R += f[u] * sM0[u * 64 + c];
            #pragma unroll
            for (int u = 0; u < 32; ++u) {
                float m = sM0[(64 + u) * 64 + c];
                U0 += f[64 + 3 * u + 0] * m;
                U1 += f[64 + 3 * u + 1] * m;
                U2 += f[64 + 3 * u + 2] * m;
            }
            __half2 h0 = __floats2half2_rn(R, U0);
            __half2 h1 = __floats2half2_rn(U1, U2);
            uint2 v;
            v.x = *(unsigned*)&h0; v.y = *(unsigned*)&h1;
            *(uint2*)(g_preh + (size_t)n * 384 + 4 * c) = v;
        } else {
            int w = h - 64;
            float P = 0.f, Q0 = 0.f, Q1 = 0.f, Q2 = 0.f;
            #pragma unroll
            for (int u = 0; u < 64; ++u) P += f[u] * sM1[u * 32 + w];
            #pragma unroll
            for (int u = 0; u < 32; ++u) {
                float m = sM1[(64 + u) * 32 + w];
                Q0 += f[64 + 3 * u + 0] * m;
                Q1 += f[64 + 3 * u + 1] * m;
                Q2 += f[64 + 3 * u + 2] * m;
            }
            __half2 h0 = __floats2half2_rn(P, Q0);
            __half2 h1 = __floats2half2_rn(Q1, Q2);
            uint2 v;
            v.x = *(unsigned*)&h0; v.y = *(unsigned*)&h1;
            *(uint2*)(g_preh + (size_t)n * 384 + 256 + 4 * w) = v;
        }
    }
}

// ---------------------------------------------------------------------------
// Gather + fused LayerNorm. Warp per node. No shuffles: uniform (broadcast)
// loads of the bucket entry serve all 32 lanes in one L1 wavefront.
// ---------------------------------------------------------------------------
__global__ __launch_bounds__(256) void gather_ln(float* __restrict__ out,
                                                 const float* __restrict__ gamma,
                                                 const float* __restrict__ beta) {
    int node = blockIdx.x * 8 + (threadIdx.x >> 5);
    int lane = threadIdx.x & 31;
    if (node >= N_NODES) return;
    int cnt = g_cursor[node];
    size_t bbase = (size_t)node * CAP;

    float ax = 0.f, ay = 0.f, c0 = 0.f, c1 = 0.f, c2 = 0.f;

    #pragma unroll 2
    for (int b = 0; b < cnt; ++b) {
        int    src = __ldg(&g_psrc[bbase + b]);     // uniform broadcast
        float4 A   = __ldg(&g_pattr[bbase + b]);    // uniform broadcast
        float e0 = A.x, ex = A.y, ey = A.z, ez = A.w;
        const __half* pb = g_preh + (size_t)src * 384;
        uint4 bg = *(const uint4*)(pb + 8 * lane);        // groups 2l, 2l+1
        uint2 sm = *(const uint2*)(pb + 256 + 4 * lane);  // group l (small)
        float2 p0 = __half22float2(*(__half2*)&bg.x);     // R(2l),  U0(2l)
        float2 p1 = __half22float2(*(__half2*)&bg.y);     // U1(2l), U2(2l)
        float2 p2 = __half22float2(*(__half2*)&bg.z);     // R(2l+1),U0(2l+1)
        float2 p3 = __half22float2(*(__half2*)&bg.w);     // U1,U2 (2l+1)
        float2 s0 = __half22float2(*(__half2*)&sm.x);     // P(l), Q0(l)
        float2 s1 = __half22float2(*(__half2*)&sm.y);     // Q1(l), Q2(l)
        ax += e0 * p0.x + ex * p0.y + ey * p1.x + ez * p1.y;
        ay += e0 * p2.x + ex * p2.y + ey * p3.x + ez * p3.y;
        c0 += ex * s0.x + e0 * s0.y;
        c1 += ey * s0.x + e0 * s1.x;
        c2 += ez * s0.x + e0 * s1.y;
    }

    // Fused LayerNorm over 160 channels
    float s = ax + ay + c0 + c1 + c2;
    #pragma unroll
    for (int o = 16; o > 0; o >>= 1) s += __shfl_xor_sync(0xFFFFFFFFu, s, o);
    float mu = s * (1.0f / 160.0f);
    float dx = ax - mu, dy = ay - mu, d0 = c0 - mu, d1 = c1 - mu, d2 = c2 - mu;
    float vs = dx * dx + dy * dy + d0 * d0 + d1 * d1 + d2 * d2;
    #pragma unroll
    for (int o = 16; o > 0; o >>= 1) vs += __shfl_xor_sync(0xFFFFFFFFu, vs, o);
    float r = rsqrtf(vs * (1.0f / 160.0f) + 1e-5f);

    float* row = out + (size_t)node * 160;
    float2 gg = ((const float2*)gamma)[lane];
    float2 bb = ((const float2*)beta)[lane];
    ((float2*)row)[lane] = make_float2(dx * r * gg.x + bb.x, dy * r * gg.y + bb.y);
    int cb = 64 + 3 * lane;
    row[cb + 0] = d0 * r * gamma[cb + 0] + beta[cb + 0];
    row[cb + 1] = d1 * r * gamma[cb + 1] + beta[cb + 1];
    row[cb + 2] = d2 * r * gamma[cb + 2] + beta[cb + 2];
}

// ---------------------------------------------------------------------------
extern "C" void kernel_launch(void* const* d_in, const int* in_sizes, int n_in,
                              void* d_out, int out_size) {
    const float* nf    = (const float*)d_in[0];
    const int*   ei    = (const int*)  d_in[1];
    const float* ea    = (const float*)d_in[2];
    const float* W0    = (const float*)d_in[4];
    const float* W1    = (const float*)d_in[5];
    const float* V0    = (const float*)d_in[8];
    const float* V1    = (const float*)d_in[9];
    const float* gamma = (const float*)d_in[10];
    const float* beta  = (const float*)d_in[11];
    float* out = (float*)d_out;

    int init_n = 96 * 64 + 96 * 32 + N_NODES;
    init_kernel<<<(init_n + 255) / 256, 256>>>(W0, W1, V0, V1);
    scatter_kernel<<<(N_EDGES + 255) / 256, 256>>>(ei, ea);
    node_pre<<<N_NODES / NPB, 384>>>(nf);
    gather_ln<<<(N_NODES + 7) / 8, 256>>>(out, gamma, beta);
}

// round 8
// speedup vs baseline: 1.8291x; 1.0399x over previous
#include <cuda_runtime.h>
#include <cuda_fp16.h>
#include <math.h>

#define N_NODES 20000
#define N_EDGES 320000
#define CAP     96      // bucket capacity per node (Poisson(16); P(deg>=96) ~ 1e-60)

__device__ float  g_M0[96 * 64];
__device__ float  g_M1[96 * 32];
// fp16 precompute, interleaved: per node 384 halves (768B):
//   [0,256):  group c (c<64) at 4c:   {R[c], U0[c], U1[c], U2[c]}
//   [256,384): group w (w<32) at 256+4w: {P[w], Q0[w], Q1[w], Q2[w]}
__device__ __half g_preh[(size_t)N_NODES * 384];   // ~15.4 MB
__device__ int    g_cursor[N_NODES];               // zeroed by init_kernel EVERY launch
__device__ int    g_psrc[(size_t)N_NODES * CAP];
__device__ float4 g_pattr[(size_t)N_NODES * CAP];

// ---------------------------------------------------------------------------
// Kernel 1: build combined matrices AND zero cursors (self-contained launch)
// ---------------------------------------------------------------------------
__global__ void init_kernel(const float* __restrict__ W0, const float* __restrict__ W1,
                            const float* __restrict__ V0, const float* __restrict__ V1) {
    int t = blockIdx.x * blockDim.x + threadIdx.x;
    if (t < 96 * 64) {
        int u = t >> 6, c = t & 63;
        float acc = 0.f;
        #pragma unroll 8
        for (int k = 0; k < 128; ++k) acc += W0[u * 128 + k] * V0[k * 64 + c];
        float s = 1.0f / sqrtf(96.0f * 128.0f);
        if (u >= 64) s *= 0.5773502691896258f;   // fold 1/sqrt(3)
        g_M0[t] = acc * s;
    } else if (t < 96 * 64 + 96 * 32) {
        int t2 = t - 96 * 64;
        int u = t2 >> 5, w = t2 & 31;
        float acc = 0.f;
        #pragma unroll 8
        for (int k = 0; k < 64; ++k) acc += W1[u * 64 + k] * V1[k * 32 + w];
        g_M1[t2] = acc * (1.0f / sqrtf(96.0f * 64.0f));
    } else if (t < 96 * 64 + 96 * 32 + N_NODES) {
        g_cursor[t - 96 * 64 - 96 * 32] = 0;
    }
}

// ---------------------------------------------------------------------------
// Kernel 2 (fused): blocks [0,1250) = node_pre; blocks [1250, ...) = scatter.
// Independent work overlapped in one grid.
// ---------------------------------------------------------------------------
#define NPB 16
#define PRE_BLOCKS (N_NODES / NPB)                   // 1250
#define SC_TPB 384
#define SC_BLOCKS ((N_EDGES + SC_TPB - 1) / SC_TPB)  // 834

__global__ __launch_bounds__(384) void fused_mid(const float* __restrict__ nf,
                                                 const int* __restrict__ ei,
                                                 const float* __restrict__ ea) {
    if (blockIdx.x >= PRE_BLOCKS) {
        // ---- scatter part ----
        int e = (blockIdx.x - PRE_BLOCKS) * SC_TPB + threadIdx.x;
        if (e < N_EDGES) {
            int src = ei[e];
            int dst = ei[N_EDGES + e];
            float4 a = ((const float4*)ea)[e];
            int pos = atomicAdd(&g_cursor[dst], 1);
            if (pos < CAP) {                        // hard safety clamp: no OOB ever
                size_t idx = (size_t)dst * CAP + pos;
                g_psrc[idx]  = src;
                g_pattr[idx] = a;
            }
        }
        return;
    }

    // ---- node_pre part: 4 passes x 4 nodes = 16 nodes/block ----
    __shared__ float sM0[96 * 64];
    __shared__ float sM1[96 * 32];
    __shared__ float sf[4 * 160];
    int t = threadIdx.x;
    for (int i = t; i < 96 * 64; i += 384) sM0[i] = g_M0[i];
    for (int i = t; i < 96 * 32; i += 384) sM1[i] = g_M1[i];
    int nb = blockIdx.x * NPB;
    int sub = t / 96, h = t - sub * 96;

    for (int pass = 0; pass < NPB / 4; ++pass) {
        int n0 = nb + pass * 4;
        __syncthreads();
        for (int i = t; i < 4 * 160; i += 384) sf[i] = nf[(size_t)n0 * 160 + i];
        __syncthreads();

        int n = n0 + sub;
        const float* f = sf + sub * 160;

        if (h < 64) {
            int c = h;
            float R = 0.f, U0 = 0.f, U1 = 0.f, U2 = 0.f;
            #pragma unroll
            for (int u = 0; u < 64; ++u) R += f[u] * sM0[u * 64 + c];
            #pragma unroll
            for (int u = 0; u < 32; ++u) {
                float m = sM0[(64 + u) * 64 + c];
                U0 += f[64 + 3 * u + 0] * m;
                U1 += f[64 + 3 * u + 1] * m;
                U2 += f[64 + 3 * u + 2] * m;
            }
            __half2 h0 = __floats2half2_rn(R, U0);
            __half2 h1 = __floats2half2_rn(U1, U2);
            uint2 v;
            v.x = *(unsigned*)&h0; v.y = *(unsigned*)&h1;
            *(uint2*)(g_preh + (size_t)n * 384 + 4 * c) = v;
        } else {
            int w = h - 64;
            float P = 0.f, Q0 = 0.f, Q1 = 0.f, Q2 = 0.f;
            #pragma unroll
            for (int u = 0; u < 64; ++u) P += f[u] * sM1[u * 32 + w];
            #pragma unroll
            for (int u = 0; u < 32; ++u) {
                float m = sM1[(64 + u) * 32 + w];
                Q0 += f[64 + 3 * u + 0] * m;
                Q1 += f[64 + 3 * u + 1] * m;
                Q2 += f[64 + 3 * u + 2] * m;
            }
            __half2 h0 = __floats2half2_rn(P, Q0);
            __half2 h1 = __floats2half2_rn(Q1, Q2);
            uint2 v;
            v.x = *(unsigned*)&h0; v.y = *(unsigned*)&h1;
            *(uint2*)(g_preh + (size_t)n * 384 + 256 + 4 * w) = v;
        }
    }
}

// ---------------------------------------------------------------------------
// Kernel 3: gather + fused LayerNorm; warp per node; uniform broadcast loads.
// ---------------------------------------------------------------------------
__global__ __launch_bounds__(256) void gather_ln(float* __restrict__ out,
                                                 const float* __restrict__ gamma,
                                                 const float* __restrict__ beta) {
    int node = blockIdx.x * 8 + (threadIdx.x >> 5);
    int lane = threadIdx.x & 31;
    if (node >= N_NODES) return;
    int cnt = g_cursor[node];
    const int*    psrc  = g_psrc  + (size_t)node * CAP;
    const float4* pattr = g_pattr + (size_t)node * CAP;

    float ax = 0.f, ay = 0.f, c0 = 0.f, c1 = 0.f, c2 = 0.f;

    #pragma unroll 2
    for (int b = 0; b < cnt; ++b) {
        int    src = __ldg(&psrc[b]);      // uniform broadcast
        float4 A   = __ldg(&pattr[b]);     // uniform broadcast
        float e0 = A.x, ex = A.y, ey = A.z, ez = A.w;
        const __half* pb = g_preh + (size_t)src * 384;
        uint4 bg = *(const uint4*)(pb + 8 * lane);        // groups 2l, 2l+1
        uint2 sm = *(const uint2*)(pb + 256 + 4 * lane);  // group l (small)
        float2 p0 = __half22float2(*(__half2*)&bg.x);     // R(2l),  U0(2l)
        float2 p1 = __half22float2(*(__half2*)&bg.y);     // U1(2l), U2(2l)
        float2 p2 = __half22float2(*(__half2*)&bg.z);     // R(2l+1),U0(2l+1)
        float2 p3 = __half22float2(*(__half2*)&bg.w);     // U1,U2 (2l+1)
        float2 s0 = __half22float2(*(__half2*)&sm.x);     // P(l), Q0(l)
        float2 s1 = __half22float2(*(__half2*)&sm.y);     // Q1(l), Q2(l)
        ax += e0 * p0.x + ex * p0.y + ey * p1.x + ez * p1.y;
        ay += e0 * p2.x + ex * p2.y + ey * p3.x + ez * p3.y;
        c0 += ex * s0.x + e0 * s0.y;
        c1 += ey * s0.x + e0 * s1.x;
        c2 += ez * s0.x + e0 * s1.y;
    }

    // Fused LayerNorm over 160 channels
    float s = ax + ay + c0 + c1 + c2;
    #pragma unroll
    for (int o = 16; o > 0; o >>= 1) s += __shfl_xor_sync(0xFFFFFFFFu, s, o);
    float mu = s * (1.0f / 160.0f);
    float dx = ax - mu, dy = ay - mu, d0 = c0 - mu, d1 = c1 - mu, d2 = c2 - mu;
    float vs = dx * dx + dy * dy + d0 * d0 + d1 * d1 + d2 * d2;
    #pragma unroll
    for (int o = 16; o > 0; o >>= 1) vs += __shfl_xor_sync(0xFFFFFFFFu, vs, o);
    float r = rsqrtf(vs * (1.0f / 160.0f) + 1e-5f);

    float* row = out + (size_t)node * 160;
    float2 gg = ((const float2*)gamma)[lane];
    float2 bb = ((const float2*)beta)[lane];
    ((float2*)row)[lane] = make_float2(dx * r * gg.x + bb.x, dy * r * gg.y + bb.y);
    int cb = 64 + 3 * lane;
    row[cb + 0] = d0 * r * gamma[cb + 0] + beta[cb + 0];
    row[cb + 1] = d1 * r * gamma[cb + 1] + beta[cb + 1];
    row[cb + 2] = d2 * r * gamma[cb + 2] + beta[cb + 2];
}

// ---------------------------------------------------------------------------
extern "C" void kernel_launch(void* const* d_in, const int* in_sizes, int n_in,
                              void* d_out, int out_size) {
    const float* nf    = (const float*)d_in[0];
    const int*   ei    = (const int*)  d_in[1];
    const float* ea    = (const float*)d_in[2];
    const float* W0    = (const float*)d_in[4];
    const float* W1    = (const float*)d_in[5];
    const float* V0    = (const float*)d_in[8];
    const float* V1    = (const float*)d_in[9];
    const float* gamma = (const float*)d_in[10];
    const float* beta  = (const float*)d_in[11];
    float* out = (float*)d_out;

    init_kernel<<<(96 * 64 + 96 * 32 + N_NODES + 255) / 256, 256>>>(W0, W1, V0, V1);
    fused_mid<<<PRE_BLOCKS + SC_BLOCKS, 384>>>(nf, ei, ea);
    gather_ln<<<(N_NODES + 7) / 8, 256>>>(out, gamma, beta);
}

// round 9
// speedup vs baseline: 1.9300x; 1.0551x over previous
#include <cuda_runtime.h>
#include <cuda_fp16.h>
#include <math.h>

#define N_NODES 20000
#define N_EDGES 320000
#define CAP     96      // bucket capacity per node (Poisson(16); P(deg>=96) ~ 1e-60)

__device__ float  g_M0[96 * 64];
__device__ float  g_M1[96 * 32];
// fp16 precompute, interleaved: per node 384 halves (768B):
//   [0,256):  group c (c<64) at 4c:   {R[c], U0[c], U1[c], U2[c]}
//   [256,384): group w (w<32) at 256+4w: {P[w], Q0[w], Q1[w], Q2[w]}
__device__ __half g_preh[(size_t)N_NODES * 384];   // ~15.4 MB
__device__ int    g_cursor[N_NODES];               // zeroed by init_kernel EVERY launch
__device__ int    g_psrc[(size_t)N_NODES * CAP];
__device__ float4 g_pattr[(size_t)N_NODES * CAP];

// ---------------------------------------------------------------------------
// Kernel 1: build M0/M1 with 4-way k-split + quad shuffle reduce; zero cursors.
// Block-aligned ranges: blocks [0,96) = M0, [96,144) = M1, [144,...) = cursors.
// ---------------------------------------------------------------------------
__global__ void init_kernel(const float* __restrict__ W0, const float* __restrict__ W1,
                            const float* __restrict__ V0, const float* __restrict__ V1) {
    int t = blockIdx.x * blockDim.x + threadIdx.x;
    if (t < 4 * 6144) {                    // M0: 6144 outputs x 4 lanes
        int out = t >> 2, l4 = t & 3;
        int u = out >> 6, c = out & 63;
        float acc = 0.f;
        int k0 = l4 * 32;
        #pragma unroll
        for (int kk = 0; kk < 32; ++kk)
            acc += W0[u * 128 + k0 + kk] * V0[(k0 + kk) * 64 + c];
        acc += __shfl_xor_sync(0xFFFFFFFFu, acc, 1);
        acc += __shfl_xor_sync(0xFFFFFFFFu, acc, 2);
        if (l4 == 0) {
            float s = 1.0f / sqrtf(96.0f * 128.0f);
            if (u >= 64) s *= 0.5773502691896258f;   // fold 1/sqrt(3)
            g_M0[out] = acc * s;
        }
    } else if (t < 4 * 9216) {             // M1: 3072 outputs x 4 lanes
        int t2 = t - 4 * 6144;
        int out = t2 >> 2, l4 = t2 & 3;
        int u = out >> 5, w = out & 31;
        float acc = 0.f;
        int k0 = l4 * 16;
        #pragma unroll
        for (int kk = 0; kk < 16; ++kk)
            acc += W1[u * 64 + k0 + kk] * V1[(k0 + kk) * 32 + w];
        acc += __shfl_xor_sync(0xFFFFFFFFu, acc, 1);
        acc += __shfl_xor_sync(0xFFFFFFFFu, acc, 2);
        if (l4 == 0) g_M1[out] = acc * (1.0f / sqrtf(96.0f * 64.0f));
    } else if (t < 4 * 9216 + N_NODES) {
        g_cursor[t - 4 * 9216] = 0;
    }
}

// ---------------------------------------------------------------------------
// accum: 4 output cols (m) x 4 nodes (f). acc[nn] += m * f[nn].
// ---------------------------------------------------------------------------
template <int ITERS>
__device__ __forceinline__ void accum4x4(const float* __restrict__ mbase, int mstride,
                                         const float* __restrict__ fbase, int fstride,
                                         float4 acc[4]) {
    #pragma unroll 8
    for (int u = 0; u < ITERS; ++u) {
        float4 m = *(const float4*)(mbase + u * mstride);
        float4 f = *(const float4*)(fbase + u * fstride);
        acc[0].x += m.x * f.x; acc[0].y += m.y * f.x; acc[0].z += m.z * f.x; acc[0].w += m.w * f.x;
        acc[1].x += m.x * f.y; acc[1].y += m.y * f.y; acc[1].z += m.z * f.y; acc[1].w += m.w * f.y;
        acc[2].x += m.x * f.z; acc[2].y += m.y * f.z; acc[2].z += m.z * f.z; acc[2].w += m.w * f.z;
        acc[3].x += m.x * f.w; acc[3].y += m.y * f.w; acc[3].z += m.z * f.w; acc[3].w += m.w * f.w;
    }
}

// ---------------------------------------------------------------------------
// Kernel 2 (fused): blocks [0,1250) = node_pre (16 nodes, register-tiled);
//                   blocks [1250,...) = scatter. Overlapped in one grid.
// Role map (warp-uniform iteration counts):
//   t in [0,64)   : R   (warps 0-1,  64 iters)  g=t/16,  h=t%16  -> cols 4h..4h+3
//   t in [64,256) : U_i (warps 2-7,  32 iters)  idx=t-64, g=idx/48, r=idx%48, i=r/16, cc=r%16
//   t in [256,288): P   (warp 8,     64 iters)  idx=t-256, g=idx/8, r=idx%8
//   t in [288,384): Q_i (warps 9-11, 32 iters)  idx=t-288, g=idx/24, r=idx%24, i=r/8, ww=r%8
// ---------------------------------------------------------------------------
#define NPB 16
#define PRE_BLOCKS (N_NODES / NPB)                   // 1250
#define SC_TPB 384
#define SC_BLOCKS ((N_EDGES + SC_TPB - 1) / SC_TPB)  // 834

__global__ __launch_bounds__(384) void fused_mid(const float* __restrict__ nf,
                                                 const int* __restrict__ ei,
                                                 const float* __restrict__ ea) {
    if (blockIdx.x >= PRE_BLOCKS) {
        // ---- scatter part ----
        int e = (blockIdx.x - PRE_BLOCKS) * SC_TPB + threadIdx.x;
        if (e < N_EDGES) {
            int src = ei[e];
            int dst = ei[N_EDGES + e];
            float4 a = ((const float4*)ea)[e];
            int pos = atomicAdd(&g_cursor[dst], 1);
            if (pos < CAP) {                        // hard safety clamp: no OOB ever
                size_t idx = (size_t)dst * CAP + pos;
                g_psrc[idx]  = src;
                g_pattr[idx] = a;
            }
        }
        return;
    }

    // ---- node_pre part ----
    __shared__ float sM0[96 * 64];      // 24 KB
    __shared__ float sM1[96 * 32];      // 12 KB
    __shared__ float sfT[160 * 16];     // 10.25 KB: transposed features [ch][node]
    int t = threadIdx.x;
    int n0 = blockIdx.x * NPB;
    for (int i = t; i < 96 * 64; i += 384) sM0[i] = g_M0[i];
    for (int i = t; i < 96 * 32; i += 384) sM1[i] = g_M1[i];
    for (int i = t; i < 16 * 160; i += 384) {
        int n = i / 160, ch = i - n * 160;
        sfT[ch * 16 + n] = nf[(size_t)(n0 + n) * 160 + i - n * 160];
    }
    __syncthreads();

    float4 acc[4] = {{0,0,0,0},{0,0,0,0},{0,0,0,0},{0,0,0,0}};
    int g, pbase;

    if (t < 64) {                                  // R
        int h = t & 15; g = t >> 4;
        pbase = 16 * h;
        accum4x4<64>(sM0 + 4 * h, 64, sfT + 4 * g, 16, acc);
    } else if (t < 256) {                          // U_i
        int idx = t - 64;
        g = idx / 48; int r = idx % 48, i = r >> 4, cc = r & 15;
        pbase = 16 * cc + 1 + i;
        accum4x4<32>(sM0 + 64 * 64 + 4 * cc, 64, sfT + (64 + i) * 16 + 4 * g, 48, acc);
    } else if (t < 288) {                          // P
        int idx = t - 256;
        g = idx >> 3; int r = idx & 7;
        pbase = 256 + 16 * r;
        accum4x4<64>(sM1 + 4 * r, 32, sfT + 4 * g, 16, acc);
    } else {                                       // Q_i
        int idx = t - 288;
        g = idx / 24; int r = idx % 24, i = r >> 3, ww = r & 7;
        pbase = 256 + 16 * ww + 1 + i;
        accum4x4<32>(sM1 + 64 * 32 + 4 * ww, 32, sfT + (64 + i) * 16 + 4 * g, 48, acc);
    }

    size_t outb = (size_t)(n0 + 4 * g) * 384 + pbase;
    #pragma unroll
    for (int nn = 0; nn < 4; ++nn) {
        __half* o = g_preh + outb + (size_t)nn * 384;
        o[0]  = __float2half_rn(acc[nn].x);
        o[4]  = __float2half_rn(acc[nn].y);
        o[8]  = __float2half_rn(acc[nn].z);
        o[12] = __float2half_rn(acc[nn].w);
    }
}

// ---------------------------------------------------------------------------
// Kernel 3: gather + fused LayerNorm; warp per node; uniform broadcast loads.
// ---------------------------------------------------------------------------
__global__ __launch_bounds__(256) void gather_ln(float* __restrict__ out,
                                                 const float* __restrict__ gamma,
                                                 const float* __restrict__ beta) {
    int node = blockIdx.x * 8 + (threadIdx.x >> 5);
    int lane = threadIdx.x & 31;
    if (node >= N_NODES) return;
    int cnt = g_cursor[node];
    const int*    psrc  = g_psrc  + (size_t)node * CAP;
    const float4* pattr = g_pattr + (size_t)node * CAP;

    float ax = 0.f, ay = 0.f, c0 = 0.f, c1 = 0.f, c2 = 0.f;

    #pragma unroll 2
    for (int b = 0; b < cnt; ++b) {
        int    src = __ldg(&psrc[b]);      // uniform broadcast
        float4 A   = __ldg(&pattr[b]);     // uniform broadcast
        float e0 = A.x, ex = A.y, ey = A.z, ez = A.w;
        const __half* pb = g_preh + (size_t)src * 384;
        uint4 bg = *(const uint4*)(pb + 8 * lane);        // groups 2l, 2l+1
        uint2 sm = *(const uint2*)(pb + 256 + 4 * lane);  // group l (small)
        float2 p0 = __half22float2(*(__half2*)&bg.x);     // R(2l),  U0(2l)
        float2 p1 = __half22float2(*(__half2*)&bg.y);     // U1(2l), U2(2l)
        float2 p2 = __half22float2(*(__half2*)&bg.z);     // R(2l+1),U0(2l+1)
        float2 p3 = __half22float2(*(__half2*)&bg.w);     // U1,U2 (2l+1)
        float2 s0 = __half22float2(*(__half2*)&sm.x);     // P(l), Q0(l)
        float2 s1 = __half22float2(*(__half2*)&sm.y);     // Q1(l), Q2(l)
        ax += e0 * p0.x + ex * p0.y + ey * p1.x + ez * p1.y;
        ay += e0 * p2.x + ex * p2.y + ey * p3.x + ez * p3.y;
        c0 += ex * s0.x + e0 * s0.y;
        c1 += ey * s0.x + e0 * s1.x;
        c2 += ez * s0.x + e0 * s1.y;
    }

    // Fused LayerNorm over 160 channels
    float s = ax + ay + c0 + c1 + c2;
    #pragma unroll
    for (int o = 16; o > 0; o >>= 1) s += __shfl_xor_sync(0xFFFFFFFFu, s, o);
    float mu = s * (1.0f / 160.0f);
    float dx = ax - mu, dy = ay - mu, d0 = c0 - mu, d1 = c1 - mu, d2 = c2 - mu;
    float vs = dx * dx + dy * dy + d0 * d0 + d1 * d1 + d2 * d2;
    #pragma unroll
    for (int o = 16; o > 0; o >>= 1) vs += __shfl_xor_sync(0xFFFFFFFFu, vs, o);
    float r = rsqrtf(vs * (1.0f / 160.0f) + 1e-5f);

    float* row = out + (size_t)node * 160;
    float2 gg = ((const float2*)gamma)[lane];
    float2 bb = ((const float2*)beta)[lane];
    ((float2*)row)[lane] = make_float2(dx * r * gg.x + bb.x, dy * r * gg.y + bb.y);
    int cb = 64 + 3 * lane;
    row[cb + 0] = d0 * r * gamma[cb + 0] + beta[cb + 0];
    row[cb + 1] = d1 * r * gamma[cb + 1] + beta[cb + 1];
    row[cb + 2] = d2 * r * gamma[cb + 2] + beta[cb + 2];
}

// ---------------------------------------------------------------------------
extern "C" void kernel_launch(void* const* d_in, const int* in_sizes, int n_in,
                              void* d_out, int out_size) {
    const float* nf    = (const float*)d_in[0];
    const int*   ei    = (const int*)  d_in[1];
    const float* ea    = (const float*)d_in[2];
    const float* W0    = (const float*)d_in[4];
    const float* W1    = (const float*)d_in[5];
    const float* V0    = (const float*)d_in[8];
    const float* V1    = (const float*)d_in[9];
    const float* gamma = (const float*)d_in[10];
    const float* beta  = (const float*)d_in[11];
    float* out = (float*)d_out;

    init_kernel<<<(4 * 9216 + N_NODES + 255) / 256, 256>>>(W0, W1, V0, V1);
    fused_mid<<<PRE_BLOCKS + SC_BLOCKS, 384>>>(nf, ei, ea);
    gather_ln<<<(N_NODES + 7) / 8, 256>>>(out, gamma, beta);
}